// round 4
// baseline (speedup 1.0000x reference)
#include <cuda_runtime.h>

#define NEGV (-1e30f)

// Static device scratch (allocation APIs are forbidden).
// Lane-major emissions: e[t][n][256], 8 slots per lane (7 used).
// T*N*256 = 12.29M floats for (1500,32) -> fits in 12M*1.048 = 12.58M.
__device__ float    g_emit[12u * 1024u * 1024u];
__device__ float    g_tot[1024];
__device__ unsigned g_ctr;   // zero-init; finisher resets each call

// ---------------------------------------------------------------------------
// Phase 1: fully parallel emission gather + relayout.
// block = (t,n); thread j -> lane = j>>3, idx = j&7, state s = 7*lane + idx.
// g_emit[(t*N+n)*256 + 8*lane + idx] = log_probs[t][n][ext_label(s)]
// Padding slots (idx==7 or s>=S) get NEGV.
// ---------------------------------------------------------------------------
__global__ void gather_kernel(const float* __restrict__ lp,      // (T,N,C)
                              const int*   __restrict__ targets, // (N*L)
                              int N, int C, int L, int S) {
    const int tn   = blockIdx.x;        // t*N + n
    const int n    = tn % N;
    const int j    = threadIdx.x;       // 0..255
    const int lane = j >> 3;
    const int idx  = j & 7;
    const int s    = 7 * lane + idx;

    float e = NEGV;
    if (idx < 7 && s < S) {
        int lab = 0;
        if (s & 1) lab = __ldg(&targets[n * L + (s >> 1)]);
        e = __ldg(lp + (size_t)tn * C + lab);
    }
    g_emit[(size_t)tn * 256 + j] = e;
}

// ---------------------------------------------------------------------------
// Phase 2: alpha recursion — ONE WARP per utterance, barrier-free.
// Lane l owns states 7l..7l+6 in registers. Left-neighbor values cross lanes
// only for i=0,1 -> two shfl_up per step. Emissions via 2x float4 loads per
// step from the lane-major scratch, PF-deep register ring.
// logaddexp3: m + log(1 + exp(mid-m) + exp(lo-m)), branchless median3.
// Last block to finish does the deterministic fixed-order reduction.
// ---------------------------------------------------------------------------
__global__ void alpha_kernel(const int* __restrict__ targets,
                             const int* __restrict__ il,
                             const int* __restrict__ tl,
                             float* __restrict__ out,
                             int N, int L) {
    __shared__ float fin[2];

    const int n    = blockIdx.x;
    const int lane = threadIdx.x;       // 32 threads = 1 warp
    const int S    = 2 * L + 1;

    const int ilen  = il[n];
    const int s_end = 2 * tl[n];

    // Skip-edge flags for the 7 owned states.
    bool skip[7];
#pragma unroll
    for (int i = 0; i < 7; ++i) {
        int s = 7 * lane + i;
        skip[i] = false;
        if (s < S && (s & 1) && s >= 3)
            skip[i] = (__ldg(&targets[n * L + (s >> 1)]) !=
                       __ldg(&targets[n * L + (s >> 1) - 1]));
    }

    const float* eb      = g_emit + (size_t)n * 256 + 8 * lane;
    const size_t estride = (size_t)N * 256;

    // ---- t = 0 ----
    float a[7];
    {
        float4 Ea = *(const float4*)(eb);
        float4 Eb = *(const float4*)(eb + 4);
        float e0[7] = {Ea.x, Ea.y, Ea.z, Ea.w, Eb.x, Eb.y, Eb.z};
#pragma unroll
        for (int i = 0; i < 7; ++i) {
            int s = 7 * lane + i;
            a[i] = (s <= 1) ? e0[i] : NEGV;
        }
    }

    // ---- emission prefetch ring ----
    const int PF = 4;
    float4 r0[PF], r1[PF];
#pragma unroll
    for (int j = 0; j < PF; ++j) {
        int tt = 1 + j;
        if (tt > ilen - 1) tt = ilen - 1;
        r0[j] = *(const float4*)(eb + (size_t)tt * estride);
        r1[j] = *(const float4*)(eb + (size_t)tt * estride + 4);
    }

    // ---- recursion (no barriers, in-warp only) ----
    int t = 1;
    while (t < ilen) {
#pragma unroll
        for (int j = 0; j < PF; ++j) {
            if (t < ilen) {                        // uniform across warp
                float4 Ea = r0[j], Eb = r1[j];
                int tp = t + PF;
                if (tp > ilen - 1) tp = ilen - 1;
                r0[j] = *(const float4*)(eb + (size_t)tp * estride);
                r1[j] = *(const float4*)(eb + (size_t)tp * estride + 4);

                float h6 = __shfl_up_sync(0xffffffffu, a[6], 1); // state 7l-1
                float h5 = __shfl_up_sync(0xffffffffu, a[5], 1); // state 7l-2
                if (lane == 0) { h5 = NEGV; h6 = NEGV; }

                float e[7] = {Ea.x, Ea.y, Ea.z, Ea.w, Eb.x, Eb.y, Eb.z};
                float na[7];
#pragma unroll
                for (int i = 0; i < 7; ++i) {
                    float x0 = a[i];
                    float x1 = (i >= 1) ? a[i - 1] : h6;
                    float x2 = (i >= 2) ? a[i - 2] : ((i == 1) ? h6 : h5);
                    x2 = skip[i] ? x2 : NEGV;

                    float hi = fmaxf(x0, fmaxf(x1, x2));
                    float lo = fminf(x0, fminf(x1, x2));
                    float md = fmaxf(fminf(x0, x1),
                                     fminf(fmaxf(x0, x1), x2));
                    na[i] = hi + __logf(1.0f + __expf(md - hi)
                                             + __expf(lo - hi)) + e[i];
                }
#pragma unroll
                for (int i = 0; i < 7; ++i) a[i] = na[i];
                ++t;
            }
        }
    }

    // ---- per-utterance final score over the two accepting states ----
    if (lane == 0) { fin[0] = NEGV; fin[1] = NEGV; }
    __syncwarp();
#pragma unroll
    for (int i = 0; i < 7; ++i) {
        int s = 7 * lane + i;
        if (s == s_end)     fin[0] = a[i];
        if (s == s_end - 1) fin[1] = a[i];
    }
    __syncwarp();

    if (lane == 0) {
        float A = fin[0], B = fin[1];
        float m = fmaxf(A, B);
        g_tot[n] = m + __logf(__expf(A - m) + __expf(B - m));
        __threadfence();
        unsigned v = atomicAdd(&g_ctr, 1);
        if (v == (unsigned)gridDim.x - 1) {   // last block: fixed-order reduce
            __threadfence();
            float acc = 0.0f;
            for (int i = 0; i < N; ++i) {
                float tt = *((volatile float*)&g_tot[i]);
                if (tt > -1e29f) acc += tt;
            }
            out[0] = -acc;
            g_ctr = 0;
        }
    }
}

extern "C" void kernel_launch(void* const* d_in, const int* in_sizes, int n_in,
                              void* d_out, int out_size) {
    const float* lp      = (const float*)d_in[0];
    const int*   targets = (const int*)d_in[1];
    const int*   il      = (const int*)d_in[2];
    const int*   tl      = (const int*)d_in[3];

    const int N = in_sizes[2];
    const int L = in_sizes[1] / N;        // 100
    const int C = 1024;                   // fixed for this problem id
    const int T = in_sizes[0] / (N * C);  // 1500
    const int S = 2 * L + 1;              // 201 (needs S <= 224)

    gather_kernel<<<T * N, 256>>>(lp, targets, N, C, L, S);
    alpha_kernel<<<N, 32>>>(targets, il, tl, (float*)d_out, N, L);
}

// round 5
// speedup vs baseline: 4.3935x; 4.3935x over previous
#include <cuda_runtime.h>
#include <cstdint>

#define NEGV (-1e30f)
#define LOG2E 1.4426950408889634f
#define LN2   0.6931471805599453f

// Static device scratch (allocation APIs are forbidden).
// Lane-major emissions in LOG2 domain: e2[t][n][256], 8 slots/lane (7 used).
__device__ float    g_emit[12u * 1024u * 1024u];
__device__ float    g_tot[1024];
__device__ unsigned g_ctr;   // zero-init; finisher resets each call

__device__ __forceinline__ float ex2f(float x) {
    float y; asm("ex2.approx.ftz.f32 %0, %1;" : "=f"(y) : "f"(x)); return y;
}
__device__ __forceinline__ float lg2f(float x) {
    float y; asm("lg2.approx.ftz.f32 %0, %1;" : "=f"(y) : "f"(x)); return y;
}

// ---------------------------------------------------------------------------
// Phase 1: parallel emission gather + relayout + log2 scaling.
// block = (t,n); thread j -> lane = j>>3, idx = j&7, state s = 7*lane + idx.
// ---------------------------------------------------------------------------
__global__ void gather_kernel(const float* __restrict__ lp,      // (T,N,C)
                              const int*   __restrict__ targets, // (N*L)
                              int N, int C, int L, int S) {
    const int tn   = blockIdx.x;
    const int n    = tn % N;
    const int j    = threadIdx.x;       // 0..255
    const int lane = j >> 3;
    const int idx  = j & 7;
    const int s    = 7 * lane + idx;

    float e = NEGV;
    if (idx < 7 && s < S) {
        int lab = 0;
        if (s & 1) lab = __ldg(&targets[n * L + (s >> 1)]);
        e = __ldg(lp + (size_t)tn * C + lab) * LOG2E;
    }
    g_emit[(size_t)tn * 256 + j] = e;
}

// ---------------------------------------------------------------------------
// Phase 2: alpha recursion — ONE WARP per utterance, barrier-free.
// Lane l owns states 7l..7l+6 in registers (log2 domain). Cross-lane halo via
// two shfl_up. Emissions streamed through a cp.async double-buffered shared
// FIFO (CHUNK steps per buffer) -> zero ring registers, full MLP.
// ---------------------------------------------------------------------------
#define CHUNK 8

__global__ void alpha_kernel(const int* __restrict__ targets,
                             const int* __restrict__ il,
                             const int* __restrict__ tl,
                             float* __restrict__ out,
                             int N, int L) {
    __shared__ float sm[2][CHUNK][256];
    __shared__ float fin[2];

    const int n    = blockIdx.x;
    const int lane = threadIdx.x;       // 32 threads = 1 warp
    const int S    = 2 * L + 1;

    const int ilen  = il[n];
    const int s_end = 2 * tl[n];

    bool skip[7];
#pragma unroll
    for (int i = 0; i < 7; ++i) {
        int s = 7 * lane + i;
        skip[i] = false;
        if (s < S && (s & 1) && s >= 3)
            skip[i] = (__ldg(&targets[n * L + (s >> 1)]) !=
                       __ldg(&targets[n * L + (s >> 1) - 1]));
    }

    const float* eb      = g_emit + (size_t)n * 256 + lane * 8;
    const size_t tstride = (size_t)N * 256;

    // ---- t = 0 init (direct loads) ----
    float a[7];
#pragma unroll
    for (int i = 0; i < 7; ++i) {
        int s = 7 * lane + i;
        a[i] = (s <= 1) ? __ldg(eb + i) : NEGV;
    }

    // ---- cp.async chunk issuer ----
    auto issue_chunk = [&](int buf, int t0) {
#pragma unroll
        for (int j = 0; j < CHUNK; ++j) {
            int tt = t0 + j;
            if (tt > ilen - 1) tt = ilen - 1;
            const float* src = eb + (size_t)tt * tstride;
            uint32_t dst = (uint32_t)__cvta_generic_to_shared(&sm[buf][j][lane * 8]);
            asm volatile(
                "cp.async.cg.shared.global [%0], [%1], 16;\n\t"
                "cp.async.cg.shared.global [%2], [%3], 16;\n\t"
                :: "r"(dst), "l"(src), "r"(dst + 16), "l"(src + 4));
        }
        asm volatile("cp.async.commit_group;" ::: "memory");
    };

    issue_chunk(0, 1);
    issue_chunk(1, 1 + CHUNK);

    // ---- recursion ----
    int t = 1, buf = 0;
    while (t < ilen) {
        asm volatile("cp.async.wait_group 1;" ::: "memory");
        __syncwarp();
#pragma unroll
        for (int j = 0; j < CHUNK; ++j) {
            if (t < ilen) {                        // uniform across warp
                float4 Ea = *(const float4*)&sm[buf][j][lane * 8];
                float4 Eb = *(const float4*)&sm[buf][j][lane * 8 + 4];
                float e[7] = {Ea.x, Ea.y, Ea.z, Ea.w, Eb.x, Eb.y, Eb.z};

                float h6 = __shfl_up_sync(0xffffffffu, a[6], 1); // state 7l-1
                float h5 = __shfl_up_sync(0xffffffffu, a[5], 1); // state 7l-2
                if (lane == 0) { h5 = NEGV; h6 = NEGV; }

#pragma unroll
                for (int i = 6; i >= 0; --i) {     // in-place, descending
                    float x0 = a[i];
                    float x1 = (i >= 1) ? a[i - 1] : h6;
                    float x2 = (i >= 2) ? a[i - 2] : ((i == 1) ? h6 : h5);
                    x2 = skip[i] ? x2 : NEGV;

                    float hi = fmaxf(x0, fmaxf(x1, x2));
                    float lo = fminf(x0, fminf(x1, x2));
                    float md = fmaxf(fminf(x0, x1),
                                     fminf(fmaxf(x0, x1), x2));
                    a[i] = hi + lg2f(1.0f + ex2f(md - hi)
                                          + ex2f(lo - hi)) + e[i];
                }
                ++t;
            }
        }
        __syncwarp();                  // done reading buf before refill
        issue_chunk(buf, t + CHUNK);   // in-flight buf covers [t, t+CHUNK)
        buf ^= 1;
    }

    // ---- per-utterance final score over the two accepting states ----
    if (lane == 0) { fin[0] = NEGV; fin[1] = NEGV; }
    __syncwarp();
#pragma unroll
    for (int i = 0; i < 7; ++i) {
        int s = 7 * lane + i;
        if (s == s_end)     fin[0] = a[i];
        if (s == s_end - 1) fin[1] = a[i];
    }
    __syncwarp();

    if (lane == 0) {
        float A = fin[0], B = fin[1];
        float m = fmaxf(A, B);
        float tot2 = m + lg2f(ex2f(A - m) + ex2f(B - m));  // log2 domain
        g_tot[n] = tot2 * LN2;
        __threadfence();
        unsigned v = atomicAdd(&g_ctr, 1);
        if (v == (unsigned)gridDim.x - 1) {   // last block: fixed-order reduce
            __threadfence();
            float acc = 0.0f;
            for (int i = 0; i < N; ++i) {
                float tt = *((volatile float*)&g_tot[i]);
                if (tt > -1e29f) acc += tt;
            }
            out[0] = -acc;
            g_ctr = 0;
        }
    }
}

extern "C" void kernel_launch(void* const* d_in, const int* in_sizes, int n_in,
                              void* d_out, int out_size) {
    const float* lp      = (const float*)d_in[0];
    const int*   targets = (const int*)d_in[1];
    const int*   il      = (const int*)d_in[2];
    const int*   tl      = (const int*)d_in[3];

    const int N = in_sizes[2];
    const int L = in_sizes[1] / N;        // 100
    const int C = 1024;                   // fixed for this problem id
    const int T = in_sizes[0] / (N * C);  // 1500
    const int S = 2 * L + 1;              // 201 (needs S <= 224)

    gather_kernel<<<T * N, 256>>>(lp, targets, N, C, L, S);
    alpha_kernel<<<N, 32>>>(targets, il, tl, (float*)d_out, N, L);
}

// round 6
// speedup vs baseline: 4.9265x; 1.1213x over previous
#include <cuda_runtime.h>
#include <cstdint>

#define NEGV (-1e30f)
#define LOG2E 1.4426950408889634f
#define LN2   0.6931471805599453f
#define CHUNK 8

// Static device scratch (allocation APIs are forbidden).
__device__ float g_emit[12u * 1024u * 1024u];  // lane-major log2 emissions
__device__ float g_alpha[1024 * 224];          // forward alpha at midpoint
__device__ float g_gamma[1024 * 224];          // backward gamma at midpoint
__device__ float g_tot[1024];

__device__ __forceinline__ float ex2f(float x) {
    float y; asm("ex2.approx.ftz.f32 %0, %1;" : "=f"(y) : "f"(x)); return y;
}
__device__ __forceinline__ float lg2f(float x) {
    float y; asm("lg2.approx.ftz.f32 %0, %1;" : "=f"(y) : "f"(x)); return y;
}
__device__ __forceinline__ float lae3(float x0, float x1, float x2) {
    float hi = fmaxf(x0, fmaxf(x1, x2));
    float lo = fminf(x0, fminf(x1, x2));
    float md = fmaxf(fminf(x0, x1), fminf(fmaxf(x0, x1), x2));
    return hi + lg2f(1.0f + ex2f(md - hi) + ex2f(lo - hi));
}

// ---------------------------------------------------------------------------
// Phase 1: parallel emission gather + relayout + log2 scaling.
// ---------------------------------------------------------------------------
__global__ void gather_kernel(const float* __restrict__ lp,
                              const int*   __restrict__ targets,
                              int N, int C, int L, int S) {
    const int tn   = blockIdx.x;
    const int n    = tn % N;
    const int j    = threadIdx.x;       // 0..255
    const int lane = j >> 3;
    const int idx  = j & 7;
    const int s    = 7 * lane + idx;

    float e = NEGV;
    if (idx < 7 && s < S) {
        int lab = 0;
        if (s & 1) lab = __ldg(&targets[n * L + (s >> 1)]);
        e = __ldg(lp + (size_t)tn * C + lab) * LOG2E;
    }
    g_emit[(size_t)tn * 256 + j] = e;
}

// ---------------------------------------------------------------------------
// Phase 2: forward + backward halves, one warp per CTA, 2N CTAs concurrent.
// ---------------------------------------------------------------------------
struct Stream {
    const float* eb;       // lane base in g_emit
    size_t       tstride;
    float (*sm)[CHUNK][256];
    int          lane;

    __device__ __forceinline__ void issue(int buf, int i0, int imax,
                                          bool descending, int tbase) {
#pragma unroll
        for (int j = 0; j < CHUNK; ++j) {
            int ii = i0 + j;
            if (ii > imax) ii = imax;
            int tt = descending ? (tbase - ii) : ii;
            const float* src = eb + (size_t)tt * tstride;
            uint32_t dst = (uint32_t)__cvta_generic_to_shared(&sm[buf][j][lane * 8]);
            asm volatile(
                "cp.async.cg.shared.global [%0], [%1], 16;\n\t"
                "cp.async.cg.shared.global [%2], [%3], 16;\n\t"
                :: "r"(dst), "l"(src), "r"(dst + 16), "l"(src + 4));
        }
        asm volatile("cp.async.commit_group;" ::: "memory");
    }
};

__global__ void fb_kernel(const int* __restrict__ targets,
                          const int* __restrict__ il,
                          const int* __restrict__ tl,
                          int N, int L) {
    __shared__ float sm[2][CHUNK][256];

    const bool fwd = (blockIdx.x < (unsigned)N);
    const int  n    = fwd ? blockIdx.x : (blockIdx.x - N);
    const int  lane = threadIdx.x;
    const int  S    = 2 * L + 1;

    const int ilen  = il[n];
    const int s_end = 2 * tl[n];
    const int m     = (ilen - 1) >> 1;      // forward covers t=0..m

    Stream st;
    st.eb      = g_emit + (size_t)n * 256 + lane * 8;
    st.tstride = (size_t)N * 256;
    st.sm      = sm;
    st.lane    = lane;

    float a[7];

    if (fwd) {
        // ---- skip-in flags (s-2 -> s) ----
        bool skip[7];
#pragma unroll
        for (int i = 0; i < 7; ++i) {
            int s = 7 * lane + i;
            skip[i] = false;
            if (s < S && (s & 1) && s >= 3)
                skip[i] = (__ldg(&targets[n * L + (s >> 1)]) !=
                           __ldg(&targets[n * L + (s >> 1) - 1]));
        }
        // ---- t = 0 ----
#pragma unroll
        for (int i = 0; i < 7; ++i) {
            int s = 7 * lane + i;
            a[i] = (s <= 1) ? __ldg(st.eb + i) : NEGV;
        }
        // ---- recursion t = 1..m ----
        if (m >= 1) {
            st.issue(0, 1, m, false, 0);
            st.issue(1, 1 + CHUNK, m, false, 0);
            int t = 1, buf = 0;
            while (t <= m) {
                asm volatile("cp.async.wait_group 1;" ::: "memory");
                __syncwarp();
#pragma unroll
                for (int j = 0; j < CHUNK; ++j) {
                    if (t <= m) {
                        float4 Ea = *(const float4*)&sm[buf][j][lane * 8];
                        float4 Eb = *(const float4*)&sm[buf][j][lane * 8 + 4];
                        float e[7] = {Ea.x, Ea.y, Ea.z, Ea.w, Eb.x, Eb.y, Eb.z};

                        float h6 = __shfl_up_sync(0xffffffffu, a[6], 1);
                        float h5 = __shfl_up_sync(0xffffffffu, a[5], 1);
                        if (lane == 0) { h5 = NEGV; h6 = NEGV; }
#pragma unroll
                        for (int i = 6; i >= 0; --i) {
                            float x0 = a[i];
                            float x1 = (i >= 1) ? a[i - 1] : h6;
                            float x2 = (i >= 2) ? a[i - 2] : ((i == 1) ? h6 : h5);
                            x2 = skip[i] ? x2 : NEGV;
                            a[i] = lae3(x0, x1, x2) + e[i];
                        }
                        ++t;
                    }
                }
                __syncwarp();
                st.issue(buf, t + CHUNK, m, false, 0);
                buf ^= 1;
            }
        }
        // ---- store alpha_m ----
#pragma unroll
        for (int i = 0; i < 7; ++i)
            g_alpha[n * 224 + 7 * lane + i] = a[i];
    } else {
        // ---- skip-out flags (s -> s+2) ----
        bool bskip[7];
#pragma unroll
        for (int i = 0; i < 7; ++i) {
            int s = 7 * lane + i;
            bskip[i] = false;
            if (s < S && (s & 1) && (s >> 1) + 1 <= L - 1)
                bskip[i] = (__ldg(&targets[n * L + (s >> 1)]) !=
                            __ldg(&targets[n * L + (s >> 1) + 1]));
        }
        if (ilen == 1) {
            // beta range empty: gamma = 0 on accepting states.
#pragma unroll
            for (int i = 0; i < 7; ++i) {
                int s = 7 * lane + i;
                a[i] = (s == s_end || (s_end >= 1 && s == s_end - 1)) ? 0.0f : NEGV;
            }
        } else {
            // ---- init beta at t = ilen-1 ----
#pragma unroll
            for (int i = 0; i < 7; ++i) {
                int s = 7 * lane + i;
                float e = __ldg(st.eb + (size_t)(ilen - 1) * st.tstride + i);
                a[i] = (s == s_end || (s_end >= 1 && s == s_end - 1)) ? e : NEGV;
            }
            // ---- recursion k = 1..K  (t = ilen-1-k down to m+1) ----
            const int K = ilen - 2 - m;
            if (K >= 1) {
                st.issue(0, 1, K, true, ilen - 1);
                st.issue(1, 1 + CHUNK, K, true, ilen - 1);
                int k = 1, buf = 0;
                while (k <= K) {
                    asm volatile("cp.async.wait_group 1;" ::: "memory");
                    __syncwarp();
#pragma unroll
                    for (int j = 0; j < CHUNK; ++j) {
                        if (k <= K) {
                            float4 Ea = *(const float4*)&sm[buf][j][lane * 8];
                            float4 Eb = *(const float4*)&sm[buf][j][lane * 8 + 4];
                            float e[7] = {Ea.x, Ea.y, Ea.z, Ea.w, Eb.x, Eb.y, Eb.z};

                            float h0 = __shfl_down_sync(0xffffffffu, a[0], 1);
                            float h1 = __shfl_down_sync(0xffffffffu, a[1], 1);
                            if (lane == 31) { h0 = NEGV; h1 = NEGV; }
#pragma unroll
                            for (int i = 0; i <= 6; ++i) {
                                float x0 = a[i];
                                float x1 = (i <= 5) ? a[i + 1] : h0;
                                float x2 = (i <= 4) ? a[i + 2] : ((i == 5) ? h0 : h1);
                                x2 = bskip[i] ? x2 : NEGV;
                                a[i] = lae3(x0, x1, x2) + e[i];
                            }
                            ++k;
                        }
                    }
                    __syncwarp();
                    st.issue(buf, k + CHUNK, K, true, ilen - 1);
                    buf ^= 1;
                }
            }
            // ---- gamma: one transition-only step (no emission) ----
            {
                float h0 = __shfl_down_sync(0xffffffffu, a[0], 1);
                float h1 = __shfl_down_sync(0xffffffffu, a[1], 1);
                if (lane == 31) { h0 = NEGV; h1 = NEGV; }
                float na[7];
#pragma unroll
                for (int i = 0; i <= 6; ++i) {
                    float x0 = a[i];
                    float x1 = (i <= 5) ? a[i + 1] : h0;
                    float x2 = (i <= 4) ? a[i + 2] : ((i == 5) ? h0 : h1);
                    x2 = bskip[i] ? x2 : NEGV;
                    na[i] = lae3(x0, x1, x2);
                }
#pragma unroll
                for (int i = 0; i < 7; ++i) a[i] = na[i];
            }
        }
        // ---- store gamma ----
#pragma unroll
        for (int i = 0; i < 7; ++i)
            g_gamma[n * 224 + 7 * lane + i] = a[i];
    }
}

// ---------------------------------------------------------------------------
// Phase 3: per-utterance logsumexp over states of alpha_m + gamma.
// ---------------------------------------------------------------------------
__global__ void combine_kernel(int N) {
    __shared__ float red[256];
    const int n = blockIdx.x;
    const int s = threadIdx.x;            // 0..255

    float v = (s < 224) ? (g_alpha[n * 224 + s] + g_gamma[n * 224 + s]) : -3.4e38f;

    // max reduce
    red[s] = v; __syncthreads();
    for (int o = 128; o > 0; o >>= 1) {
        if (s < o) red[s] = fmaxf(red[s], red[s + o]);
        __syncthreads();
    }
    float mx = red[0]; __syncthreads();

    float ev = (v > -3.3e38f) ? ex2f(v - mx) : 0.0f;
    red[s] = ev; __syncthreads();
    for (int o = 128; o > 0; o >>= 1) {
        if (s < o) red[s] += red[s + o];
        __syncthreads();
    }
    if (s == 0) g_tot[n] = (mx + lg2f(red[0])) * LN2;
}

__global__ void reduce_kernel(float* __restrict__ out, int N) {
    if (threadIdx.x == 0 && blockIdx.x == 0) {
        float acc = 0.0f;
        for (int i = 0; i < N; ++i) {
            float t = g_tot[i];
            if (t > -1e29f) acc += t;
        }
        out[0] = -acc;
    }
}

extern "C" void kernel_launch(void* const* d_in, const int* in_sizes, int n_in,
                              void* d_out, int out_size) {
    const float* lp      = (const float*)d_in[0];
    const int*   targets = (const int*)d_in[1];
    const int*   il      = (const int*)d_in[2];
    const int*   tl      = (const int*)d_in[3];

    const int N = in_sizes[2];
    const int L = in_sizes[1] / N;        // 100
    const int C = 1024;                   // fixed for this problem id
    const int T = in_sizes[0] / (N * C);  // 1500
    const int S = 2 * L + 1;              // 201 (needs S <= 217)

    gather_kernel<<<T * N, 256>>>(lp, targets, N, C, L, S);
    fb_kernel<<<2 * N, 32>>>(targets, il, tl, N, L);
    combine_kernel<<<N, 256>>>(N);
    reduce_kernel<<<1, 32>>>((float*)d_out, N);
}

// round 7
// speedup vs baseline: 6.6835x; 1.3566x over previous
#include <cuda_runtime.h>
#include <cstdint>

#define NEGV (-1e30f)
#define LOG2E 1.4426950408889634f
#define LN2   0.6931471805599453f
#define CHUNK 8

// Static device scratch (allocation APIs are forbidden).
__device__ float    g_emit[12u * 1024u * 1024u];  // lane-major log2 emissions
__device__ float    g_alpha[1024 * 224];          // forward alpha at midpoint
__device__ float    g_gamma[1024 * 224];          // backward gamma at midpoint
__device__ float    g_tot[1024];
__device__ unsigned g_ctr;                         // zero-init; reset each call

__device__ __forceinline__ float ex2f(float x) {
    float y; asm("ex2.approx.ftz.f32 %0, %1;" : "=f"(y) : "f"(x)); return y;
}
__device__ __forceinline__ float lg2f(float x) {
    float y; asm("lg2.approx.ftz.f32 %0, %1;" : "=f"(y) : "f"(x)); return y;
}
__device__ __forceinline__ float lae3(float x0, float x1, float x2) {
    float hi = fmaxf(x0, fmaxf(x1, x2));
    float lo = fminf(x0, fminf(x1, x2));
    float md = fmaxf(fminf(x0, x1), fminf(fmaxf(x0, x1), x2));
    return hi + lg2f(1.0f + ex2f(md - hi) + ex2f(lo - hi));
}

// ---------------------------------------------------------------------------
// Phase 1: parallel emission gather + relayout + log2 scaling.
// ---------------------------------------------------------------------------
__global__ void gather_kernel(const float* __restrict__ lp,
                              const int*   __restrict__ targets,
                              int N, int C, int L, int S) {
    const int tn   = blockIdx.x;
    const int n    = tn % N;
    const int j    = threadIdx.x;       // 0..255
    const int lane = j >> 3;
    const int idx  = j & 7;
    const int s    = 7 * lane + idx;

    float e = NEGV;
    if (idx < 7 && s < S) {
        int lab = 0;
        if (s & 1) lab = __ldg(&targets[n * L + (s >> 1)]);
        e = __ldg(lp + (size_t)tn * C + lab) * LOG2E;
    }
    g_emit[(size_t)tn * 256 + j] = e;
}

// ---------------------------------------------------------------------------
// Phase 2: forward + backward halves, one warp per CTA, 2N CTAs concurrent.
// cp.async double-buffered shared FIFO; whole chunk staged to registers.
// ---------------------------------------------------------------------------
__device__ __forceinline__ void issue_chunk(const float* eb, size_t tstride,
                                            float (*sm)[CHUNK][256], int lane,
                                            int buf, int i0, int imax,
                                            bool descending, int tbase) {
#pragma unroll
    for (int j = 0; j < CHUNK; ++j) {
        int ii = i0 + j;
        if (ii > imax) ii = imax;
        int tt = descending ? (tbase - ii) : ii;
        const float* src = eb + (size_t)tt * tstride;
        uint32_t dst = (uint32_t)__cvta_generic_to_shared(&sm[buf][j][lane * 8]);
        asm volatile(
            "cp.async.cg.shared.global [%0], [%1], 16;\n\t"
            "cp.async.cg.shared.global [%2], [%3], 16;\n\t"
            :: "r"(dst), "l"(src), "r"(dst + 16), "l"(src + 4));
    }
    asm volatile("cp.async.commit_group;" ::: "memory");
}

__global__ void __launch_bounds__(32, 1)
fb_kernel(const int* __restrict__ targets,
          const int* __restrict__ il,
          const int* __restrict__ tl,
          int N, int L) {
    __shared__ float sm[2][CHUNK][256];

    const bool fwd = (blockIdx.x < (unsigned)N);
    const int  n    = fwd ? blockIdx.x : (blockIdx.x - N);
    const int  lane = threadIdx.x;
    const int  S    = 2 * L + 1;

    const int ilen  = il[n];
    const int s_end = 2 * tl[n];
    const int m     = (ilen - 1) >> 1;      // forward covers t=0..m

    const float* eb      = g_emit + (size_t)n * 256 + lane * 8;
    const size_t tstride = (size_t)N * 256;

    float a[7];

    if (fwd) {
        bool skip[7];
#pragma unroll
        for (int i = 0; i < 7; ++i) {
            int s = 7 * lane + i;
            skip[i] = false;
            if (s < S && (s & 1) && s >= 3)
                skip[i] = (__ldg(&targets[n * L + (s >> 1)]) !=
                           __ldg(&targets[n * L + (s >> 1) - 1]));
        }
#pragma unroll
        for (int i = 0; i < 7; ++i) {
            int s = 7 * lane + i;
            a[i] = (s <= 1) ? __ldg(eb + i) : NEGV;
        }
        if (m >= 1) {
            issue_chunk(eb, tstride, sm, lane, 0, 1, m, false, 0);
            issue_chunk(eb, tstride, sm, lane, 1, 1 + CHUNK, m, false, 0);
            int t = 1, buf = 0;
            while (t <= m) {
                asm volatile("cp.async.wait_group 1;" ::: "memory");
                __syncwarp();
                // Stage the whole chunk's emissions into registers (MLP burst).
                float4 E0[CHUNK], E1[CHUNK];
#pragma unroll
                for (int j = 0; j < CHUNK; ++j) {
                    E0[j] = *(const float4*)&sm[buf][j][lane * 8];
                    E1[j] = *(const float4*)&sm[buf][j][lane * 8 + 4];
                }
                __syncwarp();
                issue_chunk(eb, tstride, sm, lane, buf,
                            t + 2 * CHUNK, m, false, 0);
                buf ^= 1;
#pragma unroll
                for (int j = 0; j < CHUNK; ++j) {
                    if (t <= m) {
                        float e[7] = {E0[j].x, E0[j].y, E0[j].z, E0[j].w,
                                      E1[j].x, E1[j].y, E1[j].z};
                        float h6 = __shfl_up_sync(0xffffffffu, a[6], 1);
                        float h5 = __shfl_up_sync(0xffffffffu, a[5], 1);
                        if (lane == 0) { h5 = NEGV; h6 = NEGV; }
#pragma unroll
                        for (int i = 6; i >= 0; --i) {
                            float x0 = a[i];
                            float x1 = (i >= 1) ? a[i - 1] : h6;
                            float x2 = (i >= 2) ? a[i - 2] : ((i == 1) ? h6 : h5);
                            x2 = skip[i] ? x2 : NEGV;
                            a[i] = lae3(x0, x1, x2) + e[i];
                        }
                        ++t;
                    }
                }
            }
        }
#pragma unroll
        for (int i = 0; i < 7; ++i)
            g_alpha[n * 224 + 7 * lane + i] = a[i];
    } else {
        bool bskip[7];
#pragma unroll
        for (int i = 0; i < 7; ++i) {
            int s = 7 * lane + i;
            bskip[i] = false;
            if (s < S && (s & 1) && (s >> 1) + 1 <= L - 1)
                bskip[i] = (__ldg(&targets[n * L + (s >> 1)]) !=
                            __ldg(&targets[n * L + (s >> 1) + 1]));
        }
        if (ilen == 1) {
#pragma unroll
            for (int i = 0; i < 7; ++i) {
                int s = 7 * lane + i;
                a[i] = (s == s_end || (s_end >= 1 && s == s_end - 1)) ? 0.0f : NEGV;
            }
        } else {
#pragma unroll
            for (int i = 0; i < 7; ++i) {
                int s = 7 * lane + i;
                float e = __ldg(eb + (size_t)(ilen - 1) * tstride + i);
                a[i] = (s == s_end || (s_end >= 1 && s == s_end - 1)) ? e : NEGV;
            }
            const int K = ilen - 2 - m;
            if (K >= 1) {
                issue_chunk(eb, tstride, sm, lane, 0, 1, K, true, ilen - 1);
                issue_chunk(eb, tstride, sm, lane, 1, 1 + CHUNK, K, true, ilen - 1);
                int k = 1, buf = 0;
                while (k <= K) {
                    asm volatile("cp.async.wait_group 1;" ::: "memory");
                    __syncwarp();
                    float4 E0[CHUNK], E1[CHUNK];
#pragma unroll
                    for (int j = 0; j < CHUNK; ++j) {
                        E0[j] = *(const float4*)&sm[buf][j][lane * 8];
                        E1[j] = *(const float4*)&sm[buf][j][lane * 8 + 4];
                    }
                    __syncwarp();
                    issue_chunk(eb, tstride, sm, lane, buf,
                                k + 2 * CHUNK, K, true, ilen - 1);
                    buf ^= 1;
#pragma unroll
                    for (int j = 0; j < CHUNK; ++j) {
                        if (k <= K) {
                            float e[7] = {E0[j].x, E0[j].y, E0[j].z, E0[j].w,
                                          E1[j].x, E1[j].y, E1[j].z};
                            float h0 = __shfl_down_sync(0xffffffffu, a[0], 1);
                            float h1 = __shfl_down_sync(0xffffffffu, a[1], 1);
                            if (lane == 31) { h0 = NEGV; h1 = NEGV; }
#pragma unroll
                            for (int i = 0; i <= 6; ++i) {
                                float x0 = a[i];
                                float x1 = (i <= 5) ? a[i + 1] : h0;
                                float x2 = (i <= 4) ? a[i + 2] : ((i == 5) ? h0 : h1);
                                x2 = bskip[i] ? x2 : NEGV;
                                a[i] = lae3(x0, x1, x2) + e[i];
                            }
                            ++k;
                        }
                    }
                }
            }
            // gamma: one transition-only step (no emission)
            {
                float h0 = __shfl_down_sync(0xffffffffu, a[0], 1);
                float h1 = __shfl_down_sync(0xffffffffu, a[1], 1);
                if (lane == 31) { h0 = NEGV; h1 = NEGV; }
                float na[7];
#pragma unroll
                for (int i = 0; i <= 6; ++i) {
                    float x0 = a[i];
                    float x1 = (i <= 5) ? a[i + 1] : h0;
                    float x2 = (i <= 4) ? a[i + 2] : ((i == 5) ? h0 : h1);
                    x2 = bskip[i] ? x2 : NEGV;
                    na[i] = lae3(x0, x1, x2);
                }
#pragma unroll
                for (int i = 0; i < 7; ++i) a[i] = na[i];
            }
        }
#pragma unroll
        for (int i = 0; i < 7; ++i)
            g_gamma[n * 224 + 7 * lane + i] = a[i];
    }
}

// ---------------------------------------------------------------------------
// Phase 3: per-utterance logsumexp + fixed-order global reduce (finisher).
// ---------------------------------------------------------------------------
__global__ void combine_kernel(float* __restrict__ out, int N) {
    __shared__ float red[256];
    const int n = blockIdx.x;
    const int s = threadIdx.x;            // 0..255

    float v = (s < 224) ? (g_alpha[n * 224 + s] + g_gamma[n * 224 + s]) : -3.4e38f;

    red[s] = v; __syncthreads();
    for (int o = 128; o > 0; o >>= 1) {
        if (s < o) red[s] = fmaxf(red[s], red[s + o]);
        __syncthreads();
    }
    float mx = red[0]; __syncthreads();

    float ev = (v > -3.3e38f) ? ex2f(v - mx) : 0.0f;
    red[s] = ev; __syncthreads();
    for (int o = 128; o > 0; o >>= 1) {
        if (s < o) red[s] += red[s + o];
        __syncthreads();
    }

    if (s == 0) {
        g_tot[n] = (mx + lg2f(red[0])) * LN2;
        __threadfence();
        unsigned v2 = atomicAdd(&g_ctr, 1);
        if (v2 == (unsigned)gridDim.x - 1) {     // last block: fixed-order sum
            __threadfence();
            float acc = 0.0f;
            for (int i = 0; i < N; ++i) {
                float t = *((volatile float*)&g_tot[i]);
                if (t > -1e29f) acc += t;
            }
            out[0] = -acc;
            g_ctr = 0;
        }
    }
}

extern "C" void kernel_launch(void* const* d_in, const int* in_sizes, int n_in,
                              void* d_out, int out_size) {
    const float* lp      = (const float*)d_in[0];
    const int*   targets = (const int*)d_in[1];
    const int*   il      = (const int*)d_in[2];
    const int*   tl      = (const int*)d_in[3];

    const int N = in_sizes[2];
    const int L = in_sizes[1] / N;        // 100
    const int C = 1024;                   // fixed for this problem id
    const int T = in_sizes[0] / (N * C);  // 1500
    const int S = 2 * L + 1;              // 201 (needs S <= 217)

    gather_kernel<<<T * N, 256>>>(lp, targets, N, C, L, S);
    fb_kernel<<<2 * N, 32>>>(targets, il, tl, N, L);
    combine_kernel<<<N, 256>>>((float*)d_out, N);
}